// round 17
// baseline (speedup 1.0000x reference)
#include <cuda_runtime.h>
#include <math.h>
#include <stdint.h>

#define CIN      16
#define COUT     32
#define KDIM     1024             // 64 taps * 16 cin
#define VPB      16
#define THREADS  256
#define A_STRIDE 1028

// B fragments: 128 k-steps x 4 n-tiles x 32 lanes x {b0,b1} (tf32 bits)
__device__ uint2 g_wf[128 * 4 * 32];

// dynamic smem layout (bytes):
//  A_s : VPB * A_STRIDE floats                       (65792)
//  U   : union { phase1: St4(4096)+Aux(1024)+Stf(1024);
//                phase2: P = 4*VPB*COUT floats }     ( 8192)
#define SMEM_FLOATS (VPB * A_STRIDE + 4 * VPB * COUT)

extern __shared__ float smem[];

__device__ __forceinline__ uint32_t to_tf32(float x) {
    uint32_t u;
    asm("cvt.rna.tf32.f32 %0, %1;" : "=r"(u) : "f"(x));
    return u;
}

// ================= kernel 0: pack W into tf32 B-fragments =================
__global__ void wt_kernel(const float* __restrict__ Wg) {
    const int idx = blockIdx.x * 256 + threadIdx.x;
    if (idx >= 128 * 4 * 32) return;
    const int lane = idx & 31;
    const int t    = (idx >> 5) & 3;
    const int s    = idx >> 7;
    const int g    = lane >> 2;
    const int tg   = lane & 3;
    const float v0 = Wg[(s * 8 + tg) * COUT + t * 8 + g];
    const float v1 = Wg[(s * 8 + 4 + tg) * COUT + t * 8 + g];
    g_wf[idx] = make_uint2(to_tf32(v0), to_tf32(v1));
}

// ================= main fused kernel =================
__global__ void __launch_bounds__(THREADS, 3)
cconv_kernel(const float* __restrict__ feats,
             const float* __restrict__ inp_points,
             const float* __restrict__ out_points,
             const float* __restrict__ out_extents,
             const float* __restrict__ scale_compat,
             const float* __restrict__ nbr_dist,
             const int*   __restrict__ nbr_idx,
             const int*   __restrict__ row_splits,
             const float* __restrict__ bias,
             float*       __restrict__ out,
             int n_out, int n_edges)
{
    float*  A_s   = smem;
    float*  U_s   = A_s + VPB * A_STRIDE;
    float*  P_s   = U_s;                                        // phase-2 partials
    float4* St4_s = reinterpret_cast<float4*>(U_s);             // products
    unsigned int* Aux_s = reinterpret_cast<unsigned int*>(U_s + 8 * 32 * 4);
    float*  Stf_s = U_s + 8 * 32 * 5;                           // f2 per edge

    const int tid  = threadIdx.x;
    const int warp = tid >> 5;
    const int lane = tid & 31;

    float4*       myst  = St4_s + warp * 32;
    unsigned int* myaux = Aux_s + warp * 32;
    float*        mystf = Stf_s + warp * 32;

    // ---- phase 1a (part 1): independent LDGs issued BEFORE the zero loop ----
    const int vhalf = lane >> 4;
    const int le    = lane & 15;
    const int vloc  = warp * 2 + vhalf;
    const int v     = blockIdx.x * VPB + vloc;
    const bool valid = (v < n_out);

    int   e0 = 0, cnt = 0;
    float ox = 0.f, oy = 0.f, oz = 0.f, inv_r = 1.f;
    if (valid) {
        e0  = row_splits[v];
        cnt = row_splits[v + 1] - e0;
        ox = out_points[v * 3 + 0];
        oy = out_points[v * 3 + 1];
        oz = out_points[v * 3 + 2];
        inv_r = 2.0f / out_extents[v];
    }
    int e = e0 + le;
    if (e >= n_edges) e = n_edges - 1;
    float sc = 0.f, d = 0.f;
    int nb = 0;
    if (valid) {
        sc = scale_compat[e];
        d  = nbr_dist[e];
        nb = nbr_idx[e];
    }

    // ---- zero both acc rows owned by this warp (overlaps LDG latency) ----
    {
        float4* acc4 = reinterpret_cast<float4*>(A_s + (warp * 2) * A_STRIDE);
        #pragma unroll
        for (int i = 0; i < 16; ++i)
            acc4[lane + i * 32] = make_float4(0.f, 0.f, 0.f, 0.f);
        if (lane < 8) (A_s + (warp * 2) * A_STRIDE)[2048 + lane] = 0.f;
    }

    // ---- phase 1a (part 2): geometry + product staging ----
    {
        float imp_l = 0.f, f0_l = 0.f, f1_l = 0.f, f2_l = 0.f;
        unsigned int aux_l = 0;
        if (valid) {
            float omr = 1.0f - d;
            float w6  = omr * omr * omr;
            w6 = fminf(fmaxf(w6, 0.0f), 1.0f);

            const float rx = (inp_points[nb * 3 + 0] - ox) * inv_r;
            const float ry = (inp_points[nb * 3 + 1] - oy) * inv_r;
            const float rz = (inp_points[nb * 3 + 2] - oz) * inv_r;

            const float l2   = sqrtf(rx * rx + ry * ry + rz * rz);
            const float linf = fmaxf(fabsf(rx), fmaxf(fabsf(ry), fabsf(rz)));
            const float s    = (linf > 0.0f) ? (l2 / fmaxf(linf, 1e-12f)) : 0.0f;

            const float q0 = fminf(fmaxf(rx * s, -1.0f), 1.0f);
            const float q1 = fminf(fmaxf(ry * s, -1.0f), 1.0f);
            const float q2 = fminf(fmaxf(rz * s, -1.0f), 1.0f);

            const float t0 = (q0 + 1.0f) * 1.5f;
            const float t1 = (q1 + 1.0f) * 1.5f;
            const float t2 = (q2 + 1.0f) * 1.5f;

            const float fl0 = fminf(fmaxf(floorf(t0), 0.0f), 2.0f);
            const float fl1 = fminf(fmaxf(floorf(t1), 0.0f), 2.0f);
            const float fl2 = fminf(fmaxf(floorf(t2), 0.0f), 2.0f);
            f0_l = t0 - fl0;
            f1_l = t1 - fl1;
            f2_l = t2 - fl2;
            const int cb = (((int)fl0) * 4 + (int)fl1) * 4 + (int)fl2;

            imp_l = (le < cnt) ? (sc * w6) : 0.f;
            aux_l = ((unsigned int)cb << 18) | (unsigned int)nb;
        }

        // den reduce within half-warp; all lanes get the sum
        float den = imp_l;
        #pragma unroll
        for (int off = 8; off > 0; off >>= 1)
            den += __shfl_xor_sync(0xffffffffu, den, off);
        const float impn = imp_l * ((den != 0.0f) ? (1.0f / den) : 1.0f);

        // stage corner products (impn folded): offsets 0/64/256/320 use f0,f1
        const float g0 = 1.0f - f0_l, g1 = 1.0f - f1_l;
        myst[lane]  = make_float4(g0 * g1 * impn, g0 * f1_l * impn,
                                  f0_l * g1 * impn, f0_l * f1_l * impn);
        myaux[lane] = aux_l;
        mystf[lane] = f2_l;
    }
    __syncwarp();

    // ---- phase 1b: scatter, both voxels interleaved, 4 FFMA-RMW per edge ----
    {
        const int ch    = lane & 15;
        const int chalf = lane >> 4;
        const int chb   = ch + chalf * 16;
        float* accA = A_s + (warp * 2) * A_STRIDE;
        float* accB = accA + A_STRIDE;

        #pragma unroll
        for (int hf = 0; hf < 2; ++hf) {
            unsigned int auxA[8], auxB[8];
            float fvA[8], fvB[8];
            #pragma unroll
            for (int ee = 0; ee < 8; ++ee) {
                auxA[ee] = myaux[hf * 8 + ee];
                auxB[ee] = myaux[16 + hf * 8 + ee];
                fvA[ee] = feats[(auxA[ee] & 0x3FFFFu) * CIN + ch];
                fvB[ee] = feats[(auxB[ee] & 0x3FFFFu) * CIN + ch];
            }
            #pragma unroll
            for (int ee = 0; ee < 8; ++ee) {
                {   // voxel A
                    const float4 P = myst[hf * 8 + ee];
                    const float f2 = mystf[hf * 8 + ee];
                    float* base = accA + (int)((auxA[ee] >> 18) << 4) + chb;
                    const float h2 = chalf ? f2 : (1.0f - f2);
                    const float h  = h2 * fvA[ee];
                    base[0]   = fmaf(P.x, h, base[0]);
                    base[64]  = fmaf(P.y, h, base[64]);
                    base[256] = fmaf(P.z, h, base[256]);
                    base[320] = fmaf(P.w, h, base[320]);
                }
                {   // voxel B (independent chain)
                    const float4 P = myst[16 + hf * 8 + ee];
                    const float f2 = mystf[16 + hf * 8 + ee];
                    float* base = accB + (int)((auxB[ee] >> 18) << 4) + chb;
                    const float h2 = chalf ? f2 : (1.0f - f2);
                    const float h  = h2 * fvB[ee];
                    base[0]   = fmaf(P.x, h, base[0]);
                    base[64]  = fmaf(P.y, h, base[64]);
                    base[256] = fmaf(P.z, h, base[256]);
                    base[320] = fmaf(P.w, h, base[320]);
                }
            }
        }
    }

    __syncthreads();   // phase-1 done; staging dead; P_s may be written

    // ---- phase 2: k-split tf32 MMA (16 k-steps of 8 per warp) ----
    float c[4][4];
    {
        const int g  = lane >> 2;
        const int tg = lane & 3;

        #pragma unroll
        for (int t = 0; t < 4; ++t)
            #pragma unroll
            for (int j = 0; j < 4; ++j) c[t][j] = 0.f;

        const float* Ar0 = A_s + g * A_STRIDE;
        const float* Ar1 = A_s + (g + 8) * A_STRIDE;
        const uint2* bwp = g_wf + (warp * 16) * 4 * 32 + lane;

        #pragma unroll 4
        for (int sl = 0; sl < 16; ++sl) {
            const int k0 = warp * 128 + sl * 8 + tg;
            const uint32_t a0 = to_tf32(Ar0[k0]);
            const uint32_t a1 = to_tf32(Ar1[k0]);
            const uint32_t a2 = to_tf32(Ar0[k0 + 4]);
            const uint32_t a3 = to_tf32(Ar1[k0 + 4]);

            #pragma unroll
            for (int t = 0; t < 4; ++t) {
                const uint2 b = bwp[(sl * 4 + t) * 32];
                asm volatile(
                    "mma.sync.aligned.m16n8k8.row.col.f32.tf32.tf32.f32 "
                    "{%0,%1,%2,%3}, {%4,%5,%6,%7}, {%8,%9}, {%0,%1,%2,%3};"
                    : "+f"(c[t][0]), "+f"(c[t][1]), "+f"(c[t][2]), "+f"(c[t][3])
                    : "r"(a0), "r"(a1), "r"(a2), "r"(a3), "r"(b.x), "r"(b.y));
            }
        }
    }

    // ---- partial combine: warps 0-3 store, warps 4-7 add in place ----
    {
        const int g    = lane >> 2;
        const int colb = (lane & 3) * 2;
        const int pw   = warp & 3;

        if (warp < 4) {
            #pragma unroll
            for (int t = 0; t < 4; ++t) {
                *reinterpret_cast<float2*>(P_s + (pw * VPB + g) * COUT + t * 8 + colb) =
                    make_float2(c[t][0], c[t][1]);
                *reinterpret_cast<float2*>(P_s + (pw * VPB + g + 8) * COUT + t * 8 + colb) =
                    make_float2(c[t][2], c[t][3]);
            }
        }
        __syncthreads();
        if (warp >= 4) {
            #pragma unroll
            for (int t = 0; t < 4; ++t) {
                float2* p0 = reinterpret_cast<float2*>(P_s + (pw * VPB + g) * COUT + t * 8 + colb);
                float2* p1 = reinterpret_cast<float2*>(P_s + (pw * VPB + g + 8) * COUT + t * 8 + colb);
                float2 v0 = *p0, v1 = *p1;
                v0.x += c[t][0]; v0.y += c[t][1];
                v1.x += c[t][2]; v1.y += c[t][3];
                *p0 = v0; *p1 = v1;
            }
        }
    }

    __syncthreads();

    // ---- reduce 4 partials, bias, relu, store (den already folded) ----
    {
        const int vv = tid >> 4;
        const int c0 = (tid & 15) * 2;
        float s0 = 0.f, s1 = 0.f;
        #pragma unroll
        for (int w = 0; w < 4; ++w) {
            const float2 p = *reinterpret_cast<const float2*>(P_s + (w * VPB + vv) * COUT + c0);
            s0 += p.x;
            s1 += p.y;
        }
        const int vg = blockIdx.x * VPB + vv;
        if (vg < n_out) {
            float2 r;
            r.x = fmaxf(s0 + bias[c0 + 0], 0.0f);
            r.y = fmaxf(s1 + bias[c0 + 1], 0.0f);
            *reinterpret_cast<float2*>(out + vg * COUT + c0) = r;
        }
    }
}

extern "C" void kernel_launch(void* const* d_in, const int* in_sizes, int n_in,
                              void* d_out, int out_size)
{
    const float* feats        = (const float*)d_in[0];
    const float* inp_points   = (const float*)d_in[1];
    const float* out_points   = (const float*)d_in[2];
    const float* out_extents  = (const float*)d_in[3];
    const float* scale_compat = (const float*)d_in[4];
    const float* nbr_dist     = (const float*)d_in[5];
    const int*   nbr_idx      = (const int*)d_in[6];
    const int*   row_splits   = (const int*)d_in[7];
    const float* Wg           = (const float*)d_in[8];
    const float* bias         = (const float*)d_in[9];
    float*       out          = (float*)d_out;

    const int n_out   = in_sizes[7] - 1;
    const int n_edges = in_sizes[6];

    const size_t smem_bytes = SMEM_FLOATS * sizeof(float);
    cudaFuncSetAttribute(cconv_kernel,
                         cudaFuncAttributeMaxDynamicSharedMemorySize,
                         (int)smem_bytes);

    wt_kernel<<<(128 * 4 * 32 + 255) / 256, 256>>>(Wg);

    const int grid = (n_out + VPB - 1) / VPB;
    cconv_kernel<<<grid, THREADS, smem_bytes>>>(
        feats, inp_points, out_points, out_extents, scale_compat,
        nbr_dist, nbr_idx, row_splits, bias, out, n_out, n_edges);
}